// round 7
// baseline (speedup 1.0000x reference)
#include <cuda_runtime.h>
#include <cuda_bf16.h>
#include <cstdint>
#include <math.h>

// Problem constants
constexpr int cB   = 32;
constexpr int cN   = 256;
constexpr int cCIN = 64;
constexpr int cCH  = 128;   // C_H == C_OUT
constexpr int cR   = 5;
constexpr int cJR  = cN * cR;       // 1280
constexpr int cK2  = cJR / 2;       // 640 jr-pairs
constexpr int cXD  = 1024;

constexpr int MASK_WORDS_PER_ROW = cJR / 32;  // 40
constexpr int ATTN_TILE_I = 32;                // i-rows per block
constexpr int N_ITILES = cN / ATTN_TILE_I;     // 8
constexpr int P_STRIDE = 33;                   // padded stride of s_phi/s_plo [k2][row]
constexpr int TILE_K2 = 8;                     // k2 rows per H stage (16 jr)
constexpr int H_STRIDE = 132;                  // padded stride of staged H [k2][n]
constexpr int N_STAGES = 3;
constexpr int N_TILES = cK2 / TILE_K2;         // 80

// smem words: s_phi 640*33 + s_plo 640*33 + s_hh 3*8*132 + s_hl 3*8*132
//           + s_dst 1280 + s_src 160 + s_inv 32 + s_mask 1280
constexpr int ATTN_WORDS = cK2 * P_STRIDE * 2 + N_STAGES * TILE_K2 * H_STRIDE * 2
                           + cJR + ATTN_TILE_I * cR + ATTN_TILE_I
                           + ATTN_TILE_I * MASK_WORDS_PER_ROW;
constexpr int ATTN_SMEM = ATTN_WORDS * 4;      // 205,312 B

// ---------------- device scratch (no cudaMalloc allowed) ----------------
__device__ float    g_h[cB * cN * cR * cCH];            // (b, jr, c) fp32: 8192x640 view
__device__ unsigned g_hh[cB * cK2 * cCH];               // bf16x2 (h[2k2][c], h[2k2+1][c]) hi
__device__ unsigned g_hl[cB * cK2 * cCH];               // lo residual
__device__ float    g_atoms[cB * cN * cCH];             // layer activations (b,n,c)
__device__ float    g_src[cB * cN * cR];
__device__ float    g_dst[cB * cN * cR];
__device__ unsigned g_mask[cB * cN * MASK_WORDS_PER_ROW];
__device__ float    g_pool[cB * 2 * cCH];               // [mean(128) | max(128)] per batch

__device__ __forceinline__ float leaky(float v) { return v >= 0.f ? v : 0.2f * v; }

__device__ __forceinline__ void cp_async16(unsigned int smem_dst, const void* gsrc) {
    asm volatile("cp.async.cg.shared.global [%0], [%1], 16;\n" :: "r"(smem_dst), "l"(gsrc));
}
__device__ __forceinline__ void cp_commit() {
    asm volatile("cp.async.commit_group;\n");
}
template <int N>
__device__ __forceinline__ void cp_wait() {
    asm volatile("cp.async.wait_group %0;\n" :: "n"(N));
}

// packed f32x2 helpers (kept for the GEMM kernel)
__device__ __forceinline__ unsigned long long pack2(float lo, float hi) {
    unsigned long long r;
    asm("mov.b64 %0, {%1, %2};" : "=l"(r) : "f"(lo), "f"(hi));
    return r;
}
__device__ __forceinline__ void fma2(unsigned long long& d, unsigned long long a,
                                     unsigned long long b) {
    asm("fma.rn.f32x2 %0, %1, %2, %0;" : "+l"(d) : "l"(a), "l"(b));
}
__device__ __forceinline__ float2 unpack2(unsigned long long v) {
    float2 r;
    asm("mov.b64 {%0, %1}, %2;" : "=f"(r.x), "=f"(r.y) : "l"(v));
    return r;
}

// mma.m16n8k16 row.col f32.bf16.bf16.f32
__device__ __forceinline__ void mma16816(float* d, unsigned a0, unsigned a1, unsigned a2,
                                         unsigned a3, unsigned b0, unsigned b1) {
    asm volatile(
        "mma.sync.aligned.m16n8k16.row.col.f32.bf16.bf16.f32 "
        "{%0,%1,%2,%3}, {%4,%5,%6,%7}, {%8,%9}, {%0,%1,%2,%3};"
        : "+f"(d[0]), "+f"(d[1]), "+f"(d[2]), "+f"(d[3])
        : "r"(a0), "r"(a1), "r"(a2), "r"(a3), "r"(b0), "r"(b1));
}

__device__ __forceinline__ unsigned bf16pair(float a, float b) {
    unsigned short ha = __bfloat16_as_ushort(__float2bfloat16(a));
    unsigned short hb = __bfloat16_as_ushort(__float2bfloat16(b));
    return (unsigned)ha | ((unsigned)hb << 16);
}

// ---------------- 1) pack bond mask into bits ----------------
__global__ __launch_bounds__(256) void pack_mask_kernel(const int* __restrict__ bonds) {
    int w = blockIdx.x * blockDim.x + threadIdx.x;
    if (w >= cB * cN * MASK_WORDS_PER_ROW) return;
    const int4* p = reinterpret_cast<const int4*>(bonds) + w * 8;
    unsigned m = 0;
#pragma unroll
    for (int q = 0; q < 8; q++) {
        int4 v = p[q];
        m |= (v.x == 1 ? 1u : 0u) << (q * 4 + 0);
        m |= (v.y == 1 ? 1u : 0u) << (q * 4 + 1);
        m |= (v.z == 1 ? 1u : 0u) << (q * 4 + 2);
        m |= (v.w == 1 ? 1u : 0u) << (q * 4 + 3);
    }
    g_mask[w] = m;
}

// ---------------- 2) h = A @ W + bias   (M=8192, N=640, K=64/128) ----------------
template <int K>
__global__ __launch_bounds__(256) void gemm_bias_kernel(const float* __restrict__ A,
                                                        const float* __restrict__ W,
                                                        const float* __restrict__ bias) {
    __shared__ float As[16][64];
    __shared__ float Bs[16][64];
    const int t  = threadIdx.x;
    const int tx = t & 15, ty = t >> 4;
    const int bm = blockIdx.y * 64, bn = blockIdx.x * 64;

    unsigned long long accp[4][2];
#pragma unroll
    for (int i = 0; i < 4; i++) { accp[i][0] = 0ull; accp[i][1] = 0ull; }

    const int arow = t >> 2, akq = t & 3;
    const int bkr = t >> 4, bn4 = t & 15;

    for (int bk = 0; bk < K; bk += 16) {
        float4 av = *reinterpret_cast<const float4*>(&A[(bm + arow) * K + bk + akq * 4]);
        As[akq * 4 + 0][arow] = av.x;
        As[akq * 4 + 1][arow] = av.y;
        As[akq * 4 + 2][arow] = av.z;
        As[akq * 4 + 3][arow] = av.w;
        *reinterpret_cast<float4*>(&Bs[bkr][bn4 * 4]) =
            *reinterpret_cast<const float4*>(&W[(bk + bkr) * 640 + bn + bn4 * 4]);
        __syncthreads();
#pragma unroll
        for (int k = 0; k < 16; k++) {
            float4 a  = *reinterpret_cast<float4*>(&As[k][ty * 4]);
            float4 bv = *reinterpret_cast<float4*>(&Bs[k][tx * 4]);
            unsigned long long b01 = pack2(bv.x, bv.y), b23 = pack2(bv.z, bv.w);
            unsigned long long pa;
            pa = pack2(a.x, a.x); fma2(accp[0][0], pa, b01); fma2(accp[0][1], pa, b23);
            pa = pack2(a.y, a.y); fma2(accp[1][0], pa, b01); fma2(accp[1][1], pa, b23);
            pa = pack2(a.z, a.z); fma2(accp[2][0], pa, b01); fma2(accp[2][1], pa, b23);
            pa = pack2(a.w, a.w); fma2(accp[3][0], pa, b01); fma2(accp[3][1], pa, b23);
        }
        __syncthreads();
    }
    float4 bb = *reinterpret_cast<const float4*>(&bias[bn + tx * 4]);
#pragma unroll
    for (int i = 0; i < 4; i++) {
        float2 lo = unpack2(accp[i][0]), hi = unpack2(accp[i][1]);
        float4 o;
        o.x = lo.x + bb.x; o.y = lo.y + bb.y;
        o.z = hi.x + bb.z; o.w = hi.y + bb.w;
        *reinterpret_cast<float4*>(&g_h[(bm + ty * 4 + i) * 640 + bn + tx * 4]) = o;
    }
}

// ---------------- 2b) split H into k-paired bf16 hi/lo ----------------
// word (b, k2, c) = (bf16(h[b][2k2][c]), bf16(h[b][2k2+1][c])); lo = residual.
__global__ __launch_bounds__(256) void split_h_kernel() {
    int idx = blockIdx.x * 256 + threadIdx.x;           // (b, k2, n4): 32*640*32
    if (idx >= cB * cK2 * 32) return;
    int n4 = idx & 31;
    int k2 = (idx >> 5) % cK2;
    int b  = idx / (cK2 * 32);
    const float* h0 = &g_h[(size_t)b * cJR * cCH + (2 * k2) * cCH + n4 * 4];
    float4 r0 = *reinterpret_cast<const float4*>(h0);
    float4 r1 = *reinterpret_cast<const float4*>(h0 + cCH);
    unsigned hi[4], lo[4];
    float a0[4] = {r0.x, r0.y, r0.z, r0.w};
    float a1[4] = {r1.x, r1.y, r1.z, r1.w};
#pragma unroll
    for (int i = 0; i < 4; i++) {
        __nv_bfloat16 h0b = __float2bfloat16(a0[i]);
        __nv_bfloat16 h1b = __float2bfloat16(a1[i]);
        float l0 = a0[i] - __bfloat162float(h0b);
        float l1 = a1[i] - __bfloat162float(h1b);
        hi[i] = (unsigned)__bfloat16_as_ushort(h0b) | ((unsigned)__bfloat16_as_ushort(h1b) << 16);
        lo[i] = (unsigned)__bfloat16_as_ushort(__float2bfloat16(l0))
              | ((unsigned)__bfloat16_as_ushort(__float2bfloat16(l1)) << 16);
    }
    unsigned dstoff = (unsigned)b * (cK2 * cCH) + k2 * cCH + n4 * 4;
    *reinterpret_cast<uint4*>(&g_hh[dstoff]) = make_uint4(hi[0], hi[1], hi[2], hi[3]);
    *reinterpret_cast<uint4*>(&g_hl[dstoff]) = make_uint4(lo[0], lo[1], lo[2], lo[3]);
}

// ---------------- 3) src/dst projections ----------------
__global__ __launch_bounds__(160) void src_dst_kernel(const float* __restrict__ a) {
    const int bn   = blockIdx.x;
    const int r    = threadIdx.x >> 5;
    const int lane = threadIdx.x & 31;
    const float* hrow = &g_h[(size_t)bn * cR * cCH + r * cCH];
    float4 hv = *reinterpret_cast<const float4*>(&hrow[lane * 4]);
    float4 as = *reinterpret_cast<const float4*>(&a[r * (2 * cCH) + lane * 4]);
    float4 ad = *reinterpret_cast<const float4*>(&a[r * (2 * cCH) + cCH + lane * 4]);
    float s = hv.x * as.x + hv.y * as.y + hv.z * as.z + hv.w * as.w;
    float d = hv.x * ad.x + hv.y * ad.y + hv.z * ad.z + hv.w * ad.w;
#pragma unroll
    for (int o = 16; o; o >>= 1) {
        s += __shfl_xor_sync(0xffffffffu, s, o);
        d += __shfl_xor_sync(0xffffffffu, d, o);
    }
    if (lane == 0) {
        g_src[bn * cR + r] = s;
        g_dst[bn * cR + r] = d;
    }
}

// ---------------- 4) fused masked softmax + aggregation (HMMA bf16 3-term) --------
// Block: (b, 32-row i-tile), 256 threads / 8 warps.
// Phase 1: p = mask ? exp(leaky(src+dst)) : 0 (no max-sub; logits are O(1)),
//          stored as bf16 hi/lo, k-paired: s_phi[k2*33+row] = (p[2k2], p[2k2+1]).
// Phase 2: out = P @ H via mma.m16n8k16: d += Ahi*Bhi + Ahi*Blo + Alo*Bhi.
// Warp w: rows (w>>2)*16..+15, cols (w&3)*32..+31. H streamed via 3-stage cp.async.
template <bool LEAKY_OUT>
__global__ __launch_bounds__(256) void attn_kernel() {
    extern __shared__ float sm[];
    unsigned* s_phi  = reinterpret_cast<unsigned*>(sm);            // 640*33
    unsigned* s_plo  = s_phi + cK2 * P_STRIDE;                     // 640*33
    unsigned* s_hh   = s_plo + cK2 * P_STRIDE;                     // 3*8*132
    unsigned* s_hl   = s_hh + N_STAGES * TILE_K2 * H_STRIDE;       // 3*8*132
    float*    s_dst  = reinterpret_cast<float*>(s_hl + N_STAGES * TILE_K2 * H_STRIDE);
    float*    s_src  = s_dst + cJR;                                // 160
    float*    s_inv  = s_src + ATTN_TILE_I * cR;                   // 32
    unsigned* s_mask = reinterpret_cast<unsigned*>(s_inv + ATTN_TILE_I);

    const int b  = blockIdx.x >> 3;
    const int i0 = (blockIdx.x & 7) * ATTN_TILE_I;
    const int t  = threadIdx.x;

    const unsigned* hh_g = &g_hh[(size_t)b * cK2 * cCH];
    const unsigned* hl_g = &g_hl[(size_t)b * cK2 * cCH];
    const unsigned s_hh_addr = (unsigned)__cvta_generic_to_shared(s_hh);
    const unsigned s_hl_addr = (unsigned)__cvta_generic_to_shared(s_hl);

    const int prow = t >> 5, pc4 = t & 31;   // prefetch mapping: 8 rows x 32 quad-cols

    // prefetch tiles 0 and 1
#pragma unroll
    for (int tile = 0; tile < 2; tile++) {
        unsigned doff = (tile * (TILE_K2 * H_STRIDE) + prow * H_STRIDE + pc4 * 4) * 4;
        unsigned soff = (tile * TILE_K2 + prow) * cCH + pc4 * 4;
        cp_async16(s_hh_addr + doff, hh_g + soff);
        cp_async16(s_hl_addr + doff, hl_g + soff);
        cp_commit();
    }

    for (int idx = t; idx < cJR; idx += 256) s_dst[idx] = g_dst[b * cJR + idx];
    if (t < ATTN_TILE_I * cR) s_src[t] = g_src[(b * cN + i0) * cR + t];
    for (int idx = t; idx < ATTN_TILE_I * MASK_WORDS_PER_ROW; idx += 256)
        s_mask[idx] = g_mask[(b * cN + i0) * MASK_WORDS_PER_ROW + idx];
    __syncthreads();

    // ---- phase 1 (8 threads / row): exp + split-bf16 store + sum
    {
        const int row = t >> 3, l8 = t & 7;
        const float* srcr = s_src + row * cR;
        const unsigned* mrow = s_mask + row * MASK_WORDS_PER_ROW;
        unsigned short* phi16 = reinterpret_cast<unsigned short*>(s_phi);
        unsigned short* plo16 = reinterpret_cast<unsigned short*>(s_plo);

        float sum = 0.f;
        int r = l8 % 5;
        for (int e = l8; e < cJR; e += 8) {
            float v = leaky(srcr[r] + s_dst[e]);
            unsigned bit = (mrow[e >> 5] >> (e & 31)) & 1u;
            float p = bit ? __expf(v) : 0.f;
            sum += p;
            __nv_bfloat16 hb = __float2bfloat16(p);
            float rem = p - __bfloat162float(hb);
            __nv_bfloat16 lb = __float2bfloat16(rem);
            unsigned hw = ((e >> 1) * P_STRIDE + row) * 2 + (e & 1);
            phi16[hw] = __bfloat16_as_ushort(hb);
            plo16[hw] = __bfloat16_as_ushort(lb);
            r += 3; if (r >= 5) r -= 5;
        }
#pragma unroll
        for (int o = 4; o; o >>= 1) sum += __shfl_xor_sync(0xffffffffu, sum, o);
        if (l8 == 0) s_inv[row] = 1.f / sum;
    }

    // ---- phase 2: MMA mainloop
    {
        const int w    = t >> 5;
        const int lane = t & 31;
        const int rw   = w >> 2;             // row group (16 rows)
        const int cw   = w & 3;              // col group (32 cols)
        const int g    = lane >> 2;
        const int tg   = lane & 3;
        const int row0 = rw * 16 + g;

        float d[4][4];
#pragma unroll
        for (int s4 = 0; s4 < 4; s4++)
#pragma unroll
            for (int i = 0; i < 4; i++) d[s4][i] = 0.f;

        for (int tile = 0; tile < N_TILES; tile++) {
            cp_wait<1>();
            __syncthreads();   // tile data ready; compute of tile-1 done block-wide
            if (tile + 2 < N_TILES) {
                unsigned stg = (tile + 2) % N_STAGES;
                unsigned doff = (stg * (TILE_K2 * H_STRIDE) + prow * H_STRIDE + pc4 * 4) * 4;
                unsigned soff = ((tile + 2) * TILE_K2 + prow) * cCH + pc4 * 4;
                cp_async16(s_hh_addr + doff, hh_g + soff);
                cp_async16(s_hl_addr + doff, hl_g + soff);
            }
            cp_commit();

            const int k2b = tile * TILE_K2;
            const unsigned* hhT = s_hh + (tile % N_STAGES) * (TILE_K2 * H_STRIDE);
            const unsigned* hlT = s_hl + (tile % N_STAGES) * (TILE_K2 * H_STRIDE);

            unsigned ahi0 = s_phi[(k2b + tg) * P_STRIDE + row0];
            unsigned ahi1 = s_phi[(k2b + tg) * P_STRIDE + row0 + 8];
            unsigned ahi2 = s_phi[(k2b + tg + 4) * P_STRIDE + row0];
            unsigned ahi3 = s_phi[(k2b + tg + 4) * P_STRIDE + row0 + 8];
            unsigned alo0 = s_plo[(k2b + tg) * P_STRIDE + row0];
            unsigned alo1 = s_plo[(k2b + tg) * P_STRIDE + row0 + 8];
            unsigned alo2 = s_plo[(k2b + tg + 4) * P_STRIDE + row0];
            unsigned alo3 = s_plo[(k2b + tg + 4) * P_STRIDE + row0 + 8];

#pragma unroll
            for (int s4 = 0; s4 < 4; s4++) {
                const int n = cw * 32 + s4 * 8 + g;
                unsigned bh0 = hhT[tg * H_STRIDE + n];
                unsigned bh1 = hhT[(tg + 4) * H_STRIDE + n];
                unsigned bl0 = hlT[tg * H_STRIDE + n];
                unsigned bl1 = hlT[(tg + 4) * H_STRIDE + n];
                mma16816(d[s4], ahi0, ahi1, ahi2, ahi3, bh0, bh1);
                mma16816(d[s4], ahi0, ahi1, ahi2, ahi3, bl0, bl1);
                mma16816(d[s4], alo0, alo1, alo2, alo3, bh0, bh1);
            }
        }

        // epilogue: normalize, leaky, store
        const int r0 = row0, r1 = row0 + 8;
        const float inv0 = s_inv[r0], inv1 = s_inv[r1];
#pragma unroll
        for (int s4 = 0; s4 < 4; s4++) {
            const int c = cw * 32 + s4 * 8 + 2 * tg;
            float o00 = d[s4][0] * inv0, o01 = d[s4][1] * inv0;
            float o10 = d[s4][2] * inv1, o11 = d[s4][3] * inv1;
            if (LEAKY_OUT) {
                o00 = leaky(o00); o01 = leaky(o01);
                o10 = leaky(o10); o11 = leaky(o11);
            }
            *reinterpret_cast<float2*>(&g_atoms[(b * cN + i0 + r0) * cCH + c]) =
                make_float2(o00, o01);
            *reinterpret_cast<float2*>(&g_atoms[(b * cN + i0 + r1) * cCH + c]) =
                make_float2(o10, o11);
        }
    }
}

// ---------------- 5) mean/max pooling over nodes ----------------
__global__ __launch_bounds__(512) void pool_kernel() {
    __shared__ float s_sum[4][cCH];
    __shared__ float s_max[4][cCH];
    const int b  = blockIdx.x;
    const int c  = threadIdx.x & 127;
    const int ch = threadIdx.x >> 7;
    float sum = 0.f, mx = -3.4e38f;
    for (int n = ch * 64; n < ch * 64 + 64; n++) {
        float v = g_atoms[(b * cN + n) * cCH + c];
        sum += v;
        mx = fmaxf(mx, v);
    }
    s_sum[ch][c] = sum;
    s_max[ch][c] = mx;
    __syncthreads();
    if (ch == 0) {
        sum = (s_sum[0][c] + s_sum[1][c]) + (s_sum[2][c] + s_sum[3][c]);
        mx = fmaxf(fmaxf(s_max[0][c], s_max[1][c]), fmaxf(s_max[2][c], s_max[3][c]));
        g_pool[b * 256 + c] = sum * (1.f / 256.f);
        g_pool[b * 256 + cCH + c] = mx;
    }
}

// ---------------- 6) final MLP (block per batch) ----------------
__global__ __launch_bounds__(256) void mlp_kernel(const float* __restrict__ x,
                                                  const float* __restrict__ We1, const float* __restrict__ be1,
                                                  const float* __restrict__ We2, const float* __restrict__ be2,
                                                  const float* __restrict__ We3, const float* __restrict__ be3,
                                                  float* __restrict__ out) {
    __shared__ float s_z[cXD + 256];
    __shared__ float s_h1[256];
    __shared__ float s_h2[32];
    const int b = blockIdx.x, t = threadIdx.x;
    for (int i = t; i < cXD; i += 256) s_z[i] = x[b * cXD + i];
    s_z[cXD + t] = g_pool[b * 256 + t];
    __syncthreads();
    {
        float a0 = 0.f, a1 = 0.f, a2 = 0.f, a3 = 0.f;
#pragma unroll 2
        for (int k = 0; k < cXD + 256; k += 4) {
            a0 += s_z[k + 0] * We1[(k + 0) * 256 + t];
            a1 += s_z[k + 1] * We1[(k + 1) * 256 + t];
            a2 += s_z[k + 2] * We1[(k + 2) * 256 + t];
            a3 += s_z[k + 3] * We1[(k + 3) * 256 + t];
        }
        float v = (a0 + a1) + (a2 + a3) + be1[t];
        s_h1[t] = leaky(v);
    }
    __syncthreads();
    if (t < 32) {
        float c0 = 0.f, c1 = 0.f, c2 = 0.f, c3 = 0.f;
        for (int k = 0; k < 256; k += 4) {
            c0 += s_h1[k + 0] * We2[(k + 0) * 32 + t];
            c1 += s_h1[k + 1] * We2[(k + 1) * 32 + t];
            c2 += s_h1[k + 2] * We2[(k + 2) * 32 + t];
            c3 += s_h1[k + 3] * We2[(k + 3) * 32 + t];
        }
        float u = (c0 + c1) + (c2 + c3) + be2[t];
        s_h2[t] = leaky(u);
    }
    __syncthreads();
    if (t < 32) {
        float p = s_h2[t] * We3[t];
#pragma unroll
        for (int o = 16; o; o >>= 1) p += __shfl_xor_sync(0xffffffffu, p, o);
        if (t == 0) out[b] = p + be3[0];
    }
}

// ---------------- launch ----------------
extern "C" void kernel_launch(void* const* d_in, const int* in_sizes, int n_in,
                              void* d_out, int out_size) {
    const float* x       = (const float*)d_in[0];
    const float* y_atoms = (const float*)d_in[1];
    const int*   y_bonds = (const int*)d_in[2];
    const float* W1 = (const float*)d_in[3];
    const float* b1 = (const float*)d_in[4];
    const float* a1 = (const float*)d_in[5];
    const float* W2 = (const float*)d_in[6];
    const float* b2 = (const float*)d_in[7];
    const float* a2 = (const float*)d_in[8];
    const float* W3 = (const float*)d_in[9];
    const float* b3 = (const float*)d_in[10];
    const float* a3 = (const float*)d_in[11];
    const float* We1 = (const float*)d_in[12];
    const float* be1 = (const float*)d_in[13];
    const float* We2 = (const float*)d_in[14];
    const float* be2 = (const float*)d_in[15];
    const float* We3 = (const float*)d_in[16];
    const float* be3 = (const float*)d_in[17];
    float* out = (float*)d_out;

    cudaFuncSetAttribute((const void*)attn_kernel<true>,
                         cudaFuncAttributeMaxDynamicSharedMemorySize, ATTN_SMEM);
    cudaFuncSetAttribute((const void*)attn_kernel<false>,
                         cudaFuncAttributeMaxDynamicSharedMemorySize, ATTN_SMEM);

    float* atoms_ptr = nullptr;
    cudaGetSymbolAddress((void**)&atoms_ptr, g_atoms);

    const dim3 gemm_grid(10, 128);
    const int attn_grid  = cB * N_ITILES;                 // 256
    const int split_grid = (cB * cK2 * 32 + 255) / 256;   // 2560

    pack_mask_kernel<<<(cB * cN * MASK_WORDS_PER_ROW + 255) / 256, 256>>>(y_bonds);

    // layer 1
    gemm_bias_kernel<cCIN><<<gemm_grid, 256>>>(y_atoms, W1, b1);
    split_h_kernel<<<split_grid, 256>>>();
    src_dst_kernel<<<cB * cN, 160>>>(a1);
    attn_kernel<true><<<attn_grid, 256, ATTN_SMEM>>>();
    // layer 2
    gemm_bias_kernel<cCH><<<gemm_grid, 256>>>(atoms_ptr, W2, b2);
    split_h_kernel<<<split_grid, 256>>>();
    src_dst_kernel<<<cB * cN, 160>>>(a2);
    attn_kernel<true><<<attn_grid, 256, ATTN_SMEM>>>();
    // layer 3
    gemm_bias_kernel<cCH><<<gemm_grid, 256>>>(atoms_ptr, W3, b3);
    split_h_kernel<<<split_grid, 256>>>();
    src_dst_kernel<<<cB * cN, 160>>>(a3);
    attn_kernel<false><<<attn_grid, 256, ATTN_SMEM>>>();

    pool_kernel<<<cB, 512>>>();
    mlp_kernel<<<cB, 256>>>(x, We1, be1, We2, be2, We3, be3, out);
}

// round 8
// speedup vs baseline: 1.1851x; 1.1851x over previous
#include <cuda_runtime.h>
#include <cstdint>
#include <math.h>

// Problem constants
constexpr int cB   = 32;
constexpr int cN   = 256;
constexpr int cCIN = 64;
constexpr int cCH  = 128;   // C_H == C_OUT
constexpr int cR   = 5;
constexpr int cJR  = cN * cR;       // 1280
constexpr int cJH  = cJR / 2;       // 640 per half
constexpr int cXD  = 1024;

constexpr int MASK_WORDS_PER_ROW = cJR / 32;  // 40
constexpr int MASK_WORDS_HALF   = cJH / 32;   // 20
constexpr int ATTN_TILE_I = 32;                // i-rows per tile
constexpr int N_ITILES = cN / ATTN_TILE_I;     // 8
constexpr int P_STRIDE = 36;                   // padded stride of s_p [jr_local][row]
constexpr int TILE_JR = 8;                     // H rows per stage
constexpr int N_STAGES = 3;
constexpr int N_TILES_HALF = cJH / TILE_JR;    // 80

// smem floats: s_p 640*36 + s_dst 640 + s_src 160 + s_h 3*8*128
constexpr int ATTN_SMEM = (cJH * P_STRIDE + cJH + ATTN_TILE_I * cR
                           + N_STAGES * TILE_JR * cCH) * 4;   // 107,520 B -> 2 blocks/SM

// ---------------- device scratch (no cudaMalloc allowed) ----------------
__device__ float    g_h[cB * cN * cR * cCH];            // (b, jr, c): 8192 x 640
__device__ float    g_atoms[cB * cN * cCH];             // layer activations (b,n,c)
__device__ float    g_src[cB * cN * cR];
__device__ float    g_dst[cB * cN * cR];
__device__ unsigned g_mask[cB * cN * MASK_WORDS_PER_ROW];
__device__ float    g_part[cB * N_ITILES * 2 * ATTN_TILE_I * cCH];  // 8 MB partial S
__device__ float    g_psum[cB * N_ITILES * 2 * ATTN_TILE_I];        // partial sums
__device__ float    g_pool[cB * 2 * cCH];               // [mean(128) | max(128)] per batch

__device__ __forceinline__ float leaky(float v) { return v >= 0.f ? v : 0.2f * v; }

__device__ __forceinline__ void cp_async16(unsigned int smem_dst, const void* gsrc) {
    asm volatile("cp.async.cg.shared.global [%0], [%1], 16;\n" :: "r"(smem_dst), "l"(gsrc));
}
__device__ __forceinline__ void cp_commit() {
    asm volatile("cp.async.commit_group;\n");
}
template <int N>
__device__ __forceinline__ void cp_wait() {
    asm volatile("cp.async.wait_group %0;\n" :: "n"(N));
}

// packed f32x2 helpers (Blackwell FFMA2 path — PTX only)
__device__ __forceinline__ unsigned long long pack2(float lo, float hi) {
    unsigned long long r;
    asm("mov.b64 %0, {%1, %2};" : "=l"(r) : "f"(lo), "f"(hi));
    return r;
}
__device__ __forceinline__ void fma2(unsigned long long& d, unsigned long long a,
                                     unsigned long long b) {
    asm("fma.rn.f32x2 %0, %1, %2, %0;" : "+l"(d) : "l"(a), "l"(b));
}
__device__ __forceinline__ float2 unpack2(unsigned long long v) {
    float2 r;
    asm("mov.b64 {%0, %1}, %2;" : "=f"(r.x), "=f"(r.y) : "l"(v));
    return r;
}

// ---------------- 1) pack bond mask into bits ----------------
__global__ __launch_bounds__(256) void pack_mask_kernel(const int* __restrict__ bonds) {
    int w = blockIdx.x * blockDim.x + threadIdx.x;
    if (w >= cB * cN * MASK_WORDS_PER_ROW) return;
    const int4* p = reinterpret_cast<const int4*>(bonds) + w * 8;
    unsigned m = 0;
#pragma unroll
    for (int q = 0; q < 8; q++) {
        int4 v = p[q];
        m |= (v.x == 1 ? 1u : 0u) << (q * 4 + 0);
        m |= (v.y == 1 ? 1u : 0u) << (q * 4 + 1);
        m |= (v.z == 1 ? 1u : 0u) << (q * 4 + 2);
        m |= (v.w == 1 ? 1u : 0u) << (q * 4 + 3);
    }
    g_mask[w] = m;
}

// ---------------- 2) h = A @ W + bias   (M=8192, N=640, K=64/128) ----------------
template <int K>
__global__ __launch_bounds__(256) void gemm_bias_kernel(const float* __restrict__ A,
                                                        const float* __restrict__ W,
                                                        const float* __restrict__ bias) {
    __shared__ float As[16][64];
    __shared__ float Bs[16][64];
    const int t  = threadIdx.x;
    const int tx = t & 15, ty = t >> 4;
    const int bm = blockIdx.y * 64, bn = blockIdx.x * 64;

    unsigned long long accp[4][2];
#pragma unroll
    for (int i = 0; i < 4; i++) { accp[i][0] = 0ull; accp[i][1] = 0ull; }

    const int arow = t >> 2, akq = t & 3;
    const int bkr = t >> 4, bn4 = t & 15;

    for (int bk = 0; bk < K; bk += 16) {
        float4 av = *reinterpret_cast<const float4*>(&A[(bm + arow) * K + bk + akq * 4]);
        As[akq * 4 + 0][arow] = av.x;
        As[akq * 4 + 1][arow] = av.y;
        As[akq * 4 + 2][arow] = av.z;
        As[akq * 4 + 3][arow] = av.w;
        *reinterpret_cast<float4*>(&Bs[bkr][bn4 * 4]) =
            *reinterpret_cast<const float4*>(&W[(bk + bkr) * 640 + bn + bn4 * 4]);
        __syncthreads();
#pragma unroll
        for (int k = 0; k < 16; k++) {
            float4 a  = *reinterpret_cast<float4*>(&As[k][ty * 4]);
            float4 bv = *reinterpret_cast<float4*>(&Bs[k][tx * 4]);
            unsigned long long b01 = pack2(bv.x, bv.y), b23 = pack2(bv.z, bv.w);
            unsigned long long pa;
            pa = pack2(a.x, a.x); fma2(accp[0][0], pa, b01); fma2(accp[0][1], pa, b23);
            pa = pack2(a.y, a.y); fma2(accp[1][0], pa, b01); fma2(accp[1][1], pa, b23);
            pa = pack2(a.z, a.z); fma2(accp[2][0], pa, b01); fma2(accp[2][1], pa, b23);
            pa = pack2(a.w, a.w); fma2(accp[3][0], pa, b01); fma2(accp[3][1], pa, b23);
        }
        __syncthreads();
    }
    float4 bb = *reinterpret_cast<const float4*>(&bias[bn + tx * 4]);
#pragma unroll
    for (int i = 0; i < 4; i++) {
        float2 lo = unpack2(accp[i][0]), hi = unpack2(accp[i][1]);
        float4 o;
        o.x = lo.x + bb.x; o.y = lo.y + bb.y;
        o.z = hi.x + bb.z; o.w = hi.y + bb.w;
        *reinterpret_cast<float4*>(&g_h[(bm + ty * 4 + i) * 640 + bn + tx * 4]) = o;
    }
}

// ---------------- 3) src/dst projections ----------------
__global__ __launch_bounds__(160) void src_dst_kernel(const float* __restrict__ a) {
    const int bn   = blockIdx.x;
    const int r    = threadIdx.x >> 5;
    const int lane = threadIdx.x & 31;
    const float* hrow = &g_h[((size_t)bn * cR + r) * cCH];
    float4 hv = *reinterpret_cast<const float4*>(&hrow[lane * 4]);
    float4 as = *reinterpret_cast<const float4*>(&a[r * (2 * cCH) + lane * 4]);
    float4 ad = *reinterpret_cast<const float4*>(&a[r * (2 * cCH) + cCH + lane * 4]);
    float s = hv.x * as.x + hv.y * as.y + hv.z * as.z + hv.w * as.w;
    float d = hv.x * ad.x + hv.y * ad.y + hv.z * ad.z + hv.w * ad.w;
#pragma unroll
    for (int o = 16; o; o >>= 1) {
        s += __shfl_xor_sync(0xffffffffu, s, o);
        d += __shfl_xor_sync(0xffffffffu, d, o);
    }
    if (lane == 0) {
        g_src[bn * cR + r] = s;
        g_dst[bn * cR + r] = d;
    }
}

// ---------------- 4) attention partial kernel ----------------
// blockIdx.x = (b * 8 + itile) * 2 + half. Each block: 32 i-rows x 640 jr (half).
// No max-subtraction (logits are O(1); validated R7). p = mask ? exp(leaky(.)) : 0.
// Phase 2 = R5 tiling (4 rows x 4 cols / thread, broadcast p LDS.128, hv LDS.128),
// 3-stage cp.async ring, 1 barrier per 8-jr tile. Outputs unnormalized S + sum.
__global__ __launch_bounds__(256) void attn_part_kernel() {
    extern __shared__ float sm[];
    float* s_p   = sm;                         // [640][36] transposed (jr_local, row)
    float* s_dst = s_p + cJH * P_STRIDE;       // 640
    float* s_src = s_dst + cJH;                // 160
    float* s_h   = s_src + ATTN_TILE_I * cR;   // 3*8*128 (16B aligned)

    const int blk   = blockIdx.x;
    const int half  = blk & 1;
    const int itile = (blk >> 1) & 7;
    const int b     = blk >> 4;
    const int i0    = itile * ATTN_TILE_I;
    const int t     = threadIdx.x;

    const float* hbase = &g_h[((size_t)b * cJR + half * cJH) * cCH];
    const unsigned s_h_addr = (unsigned)__cvta_generic_to_shared(s_h);
    const int prow = t >> 5, pc4 = t & 31;    // 8 rows x 32 quad-cols = one 8x128 tile

    // prefetch tiles 0,1
#pragma unroll
    for (int tile = 0; tile < 2; tile++) {
        cp_async16(s_h_addr + (tile * (TILE_JR * cCH) + prow * cCH + pc4 * 4) * 4,
                   hbase + (tile * TILE_JR + prow) * cCH + pc4 * 4);
        cp_commit();
    }

    for (int idx = t; idx < cJH; idx += 256) s_dst[idx] = g_dst[b * cJR + half * cJH + idx];
    if (t < ATTN_TILE_I * cR) s_src[t] = g_src[(b * cN + i0) * cR + t];
    __syncthreads();

    // ---- phase 1 (8 threads / row): p = mask ? exp(leaky(src+dst)) : 0
    {
        const int row = t >> 3, l8 = t & 7;
        const float* srcr = s_src + row * cR;
        const unsigned* mrow = &g_mask[(b * cN + i0 + row) * MASK_WORDS_PER_ROW
                                       + half * MASK_WORDS_HALF];
        float sum = 0.f;
        int r = l8 % 5;                        // 640 % 5 == 0 so r pattern == e % 5
        for (int e = l8; e < cJH; e += 8) {
            float v = leaky(srcr[r] + s_dst[e]);
            unsigned bit = (mrow[e >> 5] >> (e & 31)) & 1u;
            float p = bit ? __expf(v) : 0.f;
            s_p[e * P_STRIDE + row] = p;
            sum += p;
            r += 3; if (r >= 5) r -= 5;
        }
#pragma unroll
        for (int o = 4; o; o >>= 1) sum += __shfl_xor_sync(0xffffffffu, sum, o);
        if (l8 == 0) g_psum[blk * ATTN_TILE_I + row] = sum;
    }

    // ---- phase 2: S[32][128] += P_half @ H_half (unnormalized)
    {
        const int c4 = t & 31;                 // cols c4*4..+3
        const int rg = t >> 5;                 // warp -> rows rg*4..+3
        unsigned long long acc[4][2];
#pragma unroll
        for (int i = 0; i < 4; i++) { acc[i][0] = 0ull; acc[i][1] = 0ull; }

        const float* pbase = s_p + rg * 4;

        for (int tile = 0; tile < N_TILES_HALF; tile++) {
            cp_wait<1>();
            __syncthreads();   // tile ready; compute of tile-1 done block-wide
            if (tile + 2 < N_TILES_HALF) {
                unsigned stg = (tile + 2) % N_STAGES;
                cp_async16(s_h_addr + (stg * (TILE_JR * cCH) + prow * cCH + pc4 * 4) * 4,
                           hbase + ((tile + 2) * TILE_JR + prow) * cCH + pc4 * 4);
            }
            cp_commit();       // exactly one group per iteration

            const float* hh = s_h + (tile % N_STAGES) * (TILE_JR * cCH) + c4 * 4;
            const float* pp = pbase + tile * TILE_JR * P_STRIDE;
#pragma unroll
            for (int j = 0; j < TILE_JR; j++) {
                float4 p4 = *reinterpret_cast<const float4*>(pp);  // warp-uniform bcast
                ulonglong2 hv = *reinterpret_cast<const ulonglong2*>(hh);
                unsigned long long pa;
                pa = pack2(p4.x, p4.x); fma2(acc[0][0], pa, hv.x); fma2(acc[0][1], pa, hv.y);
                pa = pack2(p4.y, p4.y); fma2(acc[1][0], pa, hv.x); fma2(acc[1][1], pa, hv.y);
                pa = pack2(p4.z, p4.z); fma2(acc[2][0], pa, hv.x); fma2(acc[2][1], pa, hv.y);
                pa = pack2(p4.w, p4.w); fma2(acc[3][0], pa, hv.x); fma2(acc[3][1], pa, hv.y);
                pp += P_STRIDE;
                hh += cCH;
            }
        }

        float* outb = &g_part[(size_t)blk * ATTN_TILE_I * cCH];
#pragma unroll
        for (int i = 0; i < 4; i++) {
            float2 lo = unpack2(acc[i][0]), hi = unpack2(acc[i][1]);
            *reinterpret_cast<float4*>(&outb[(rg * 4 + i) * cCH + c4 * 4]) =
                make_float4(lo.x, lo.y, hi.x, hi.y);
        }
    }
}

// ---------------- 4b) combine halves: out = (S0+S1)/(sum0+sum1), optional leaky ----
template <bool LEAKY_OUT>
__global__ __launch_bounds__(256) void combine_kernel() {
    __shared__ float rinv[ATTN_TILE_I];
    const int cidx = blockIdx.x;               // b*8+itile
    const int t = threadIdx.x;
    if (t < ATTN_TILE_I)
        rinv[t] = 1.f / (g_psum[(cidx * 2) * ATTN_TILE_I + t]
                         + g_psum[(cidx * 2 + 1) * ATTN_TILE_I + t]);
    __syncthreads();
    const float4* S0 = reinterpret_cast<const float4*>(&g_part[(size_t)(cidx * 2) * ATTN_TILE_I * cCH]);
    const float4* S1 = reinterpret_cast<const float4*>(&g_part[(size_t)(cidx * 2 + 1) * ATTN_TILE_I * cCH]);
    float4* outb = reinterpret_cast<float4*>(&g_atoms[(size_t)cidx * ATTN_TILE_I * cCH]);
#pragma unroll
    for (int q = 0; q < 4; q++) {
        int i4 = t + q * 256;                  // 1024 float4 = 32 rows x 32 quads
        float inv = rinv[i4 >> 5];
        float4 a = S0[i4], bq = S1[i4];
        float4 o = make_float4((a.x + bq.x) * inv, (a.y + bq.y) * inv,
                               (a.z + bq.z) * inv, (a.w + bq.w) * inv);
        if (LEAKY_OUT) {
            o.x = leaky(o.x); o.y = leaky(o.y); o.z = leaky(o.z); o.w = leaky(o.w);
        }
        outb[i4] = o;
    }
}

// ---------------- 5) mean/max pooling over nodes ----------------
__global__ __launch_bounds__(512) void pool_kernel() {
    __shared__ float s_sum[4][cCH];
    __shared__ float s_max[4][cCH];
    const int b  = blockIdx.x;
    const int c  = threadIdx.x & 127;
    const int ch = threadIdx.x >> 7;
    float sum = 0.f, mx = -3.4e38f;
    for (int n = ch * 64; n < ch * 64 + 64; n++) {
        float v = g_atoms[(b * cN + n) * cCH + c];
        sum += v;
        mx = fmaxf(mx, v);
    }
    s_sum[ch][c] = sum;
    s_max[ch][c] = mx;
    __syncthreads();
    if (ch == 0) {
        sum = (s_sum[0][c] + s_sum[1][c]) + (s_sum[2][c] + s_sum[3][c]);
        mx = fmaxf(fmaxf(s_max[0][c], s_max[1][c]), fmaxf(s_max[2][c], s_max[3][c]));
        g_pool[b * 256 + c] = sum * (1.f / 256.f);
        g_pool[b * 256 + cCH + c] = mx;
    }
}

// ---------------- 6) final MLP (block per batch) ----------------
__global__ __launch_bounds__(256) void mlp_kernel(const float* __restrict__ x,
                                                  const float* __restrict__ We1, const float* __restrict__ be1,
                                                  const float* __restrict__ We2, const float* __restrict__ be2,
                                                  const float* __restrict__ We3, const float* __restrict__ be3,
                                                  float* __restrict__ out) {
    __shared__ float s_z[cXD + 256];
    __shared__ float s_h1[256];
    __shared__ float s_h2[32];
    const int b = blockIdx.x, t = threadIdx.x;
    for (int i = t; i < cXD; i += 256) s_z[i] = x[b * cXD + i];
    s_z[cXD + t] = g_pool[b * 256 + t];
    __syncthreads();
    {
        float a0 = 0.f, a1 = 0.f, a2 = 0.f, a3 = 0.f;
#pragma unroll 2
        for (int k = 0; k < cXD + 256; k += 4) {
            a0 += s_z[k + 0] * We1[(k + 0) * 256 + t];
            a1 += s_z[k + 1] * We1[(k + 1) * 256 + t];
            a2 += s_z[k + 2] * We1[(k + 2) * 256 + t];
            a3 += s_z[k + 3] * We1[(k + 3) * 256 + t];
        }
        float v = (a0 + a1) + (a2 + a3) + be1[t];
        s_h1[t] = leaky(v);
    }
    __syncthreads();
    if (t < 32) {
        float c0 = 0.f, c1 = 0.f, c2 = 0.f, c3 = 0.f;
        for (int k = 0; k < 256; k += 4) {
            c0 += s_h1[k + 0] * We2[(k + 0) * 32 + t];
            c1 += s_h1[k + 1] * We2[(k + 1) * 32 + t];
            c2 += s_h1[k + 2] * We2[(k + 2) * 32 + t];
            c3 += s_h1[k + 3] * We2[(k + 3) * 32 + t];
        }
        float u = (c0 + c1) + (c2 + c3) + be2[t];
        s_h2[t] = leaky(u);
    }
    __syncthreads();
    if (t < 32) {
        float p = s_h2[t] * We3[t];
#pragma unroll
        for (int o = 16; o; o >>= 1) p += __shfl_xor_sync(0xffffffffu, p, o);
        if (t == 0) out[b] = p + be3[0];
    }
}

// ---------------- launch ----------------
extern "C" void kernel_launch(void* const* d_in, const int* in_sizes, int n_in,
                              void* d_out, int out_size) {
    const float* x       = (const float*)d_in[0];
    const float* y_atoms = (const float*)d_in[1];
    const int*   y_bonds = (const int*)d_in[2];
    const float* W1 = (const float*)d_in[3];
    const float* b1 = (const float*)d_in[4];
    const float* a1 = (const float*)d_in[5];
    const float* W2 = (const float*)d_in[6];
    const float* b2 = (const float*)d_in[7];
    const float* a2 = (const float*)d_in[8];
    const float* W3 = (const float*)d_in[9];
    const float* b3 = (const float*)d_in[10];
    const float* a3 = (const float*)d_in[11];
    const float* We1 = (const float*)d_in[12];
    const float* be1 = (const float*)d_in[13];
    const float* We2 = (const float*)d_in[14];
    const float* be2 = (const float*)d_in[15];
    const float* We3 = (const float*)d_in[16];
    const float* be3 = (const float*)d_in[17];
    float* out = (float*)d_out;

    cudaFuncSetAttribute((const void*)attn_part_kernel,
                         cudaFuncAttributeMaxDynamicSharedMemorySize, ATTN_SMEM);

    float* atoms_ptr = nullptr;
    cudaGetSymbolAddress((void**)&atoms_ptr, g_atoms);

    const dim3 gemm_grid(10, 128);
    const int attn_grid    = cB * N_ITILES * 2;   // 512 part-blocks
    const int combine_grid = cB * N_ITILES;       // 256

    pack_mask_kernel<<<(cB * cN * MASK_WORDS_PER_ROW + 255) / 256, 256>>>(y_bonds);

    // layer 1
    gemm_bias_kernel<cCIN><<<gemm_grid, 256>>>(y_atoms, W1, b1);
    src_dst_kernel<<<cB * cN, 160>>>(a1);
    attn_part_kernel<<<attn_grid, 256, ATTN_SMEM>>>();
    combine_kernel<true><<<combine_grid, 256>>>();
    // layer 2
    gemm_bias_kernel<cCH><<<gemm_grid, 256>>>(atoms_ptr, W2, b2);
    src_dst_kernel<<<cB * cN, 160>>>(a2);
    attn_part_kernel<<<attn_grid, 256, ATTN_SMEM>>>();
    combine_kernel<true><<<combine_grid, 256>>>();
    // layer 3
    gemm_bias_kernel<cCH><<<gemm_grid, 256>>>(atoms_ptr, W3, b3);
    src_dst_kernel<<<cB * cN, 160>>>(a3);
    attn_part_kernel<<<attn_grid, 256, ATTN_SMEM>>>();
    combine_kernel<false><<<combine_grid, 256>>>();

    pool_kernel<<<cB, 512>>>();
    mlp_kernel<<<cB, 256>>>(x, We1, be1, We2, be2, We3, be3, out);
}